// round 15
// baseline (speedup 1.0000x reference)
#include <cuda_runtime.h>
#include <cuda_fp16.h>
#include <math.h>
#include <stdint.h>

// ---------------- problem constants ----------------
#define BATCH 16384
#define HDIM  4096
#define DDIM  1024
#define KCB   512
#define DIN   1090
#define DINP  1152
#define RMAX  4096
#define ARG_TH 0.35f
#define NSLICE 4

#define OUT_Q    0
#define OUT_LOSS 16777216
#define OUT_PERP 16777217
#define OUT_EMB  16777218
#define OUT_CS   17301506

// ---------------- scratch (device globals; no allocation) ----------------
__device__ __half g_Xh [(size_t)BATCH * DINP];
__device__ __half g_W0h[(size_t)HDIM * DINP];
__device__ __half g_W1h[(size_t)HDIM * HDIM];
__device__ __half g_W2h[(size_t)HDIM * HDIM];
__device__ __half g_W3h[(size_t)HDIM * HDIM];
__device__ __half g_WLh[(size_t)DDIM * HDIM];
__device__ __half g_A1h[(size_t)BATCH * HDIM];
__device__ __half g_A2h[(size_t)BATCH * HDIM];
__device__ float  g_Z  [(size_t)BATCH * DDIM];
__device__ float  g_S  [(size_t)BATCH * KCB];
__device__ float  g_ET [(size_t)KCB * DDIM];
__device__ float  g_e2 [KCB];
__device__ int    g_idx[BATCH];
__device__ float  g_counts[KCB];
__device__ float  g_cs [KCB];
__device__ float  g_rowloss[BATCH];
__device__ float  g_dwT[(size_t)KCB * DDIM];
// repair path
__device__ int    g_nfix;
__device__ int    g_fixlist[RMAX];
__device__ float  g_W0f[(size_t)DINP * HDIM];
__device__ float  g_Xa [(size_t)RMAX * DINP];
__device__ float  g_Ha [(size_t)RMAX * HDIM];
__device__ float  g_Hb [(size_t)RMAX * HDIM];
__device__ float  g_Za [(size_t)RMAX * DDIM];
__device__ float  g_P  [(size_t)NSLICE * RMAX * HDIM];   // split-K partials

// ---------------- PTX helpers (all baseline sm_80-class) ----------------
__device__ __forceinline__ uint32_t smem_u32(const void* p) {
    uint32_t a;
    asm("{ .reg .u64 t; cvta.to.shared.u64 t, %1; cvt.u32.u64 %0, t; }" : "=r"(a) : "l"(p));
    return a;
}
__device__ __forceinline__ void cpa16(uint32_t s, const void* g) {
    asm volatile("cp.async.cg.shared.global [%0], [%1], 16;" :: "r"(s), "l"(g));
}
#define CP_COMMIT() asm volatile("cp.async.commit_group;" ::: "memory")

__device__ __forceinline__ void ldsm4(uint32_t* r, uint32_t a) {
    asm volatile("ldmatrix.sync.aligned.m8n8.x4.shared.b16 {%0,%1,%2,%3}, [%4];"
                 : "=r"(r[0]), "=r"(r[1]), "=r"(r[2]), "=r"(r[3]) : "r"(a));
}
__device__ __forceinline__ void mma16816(float* c, const uint32_t* a, uint32_t b0, uint32_t b1) {
    asm volatile("mma.sync.aligned.m16n8k16.row.col.f32.f16.f16.f32 "
                 "{%0,%1,%2,%3}, {%4,%5,%6,%7}, {%8,%9}, {%0,%1,%2,%3};"
                 : "+f"(c[0]), "+f"(c[1]), "+f"(c[2]), "+f"(c[3])
                 : "r"(a[0]), "r"(a[1]), "r"(a[2]), "r"(a[3]), "r"(b0), "r"(b1));
}

// ---------------- prep kernels ----------------
__global__ void zero_counts_kernel() {
    g_counts[blockIdx.x * 256 + threadIdx.x] = 0.0f;
    if (blockIdx.x == 0 && threadIdx.x == 0) g_nfix = 0;
}

__global__ void pack_x0_kernel(const float* __restrict__ obs, const float* __restrict__ act,
                               const float* __restrict__ nobs, const float* __restrict__ rew,
                               const float* __restrict__ term) {
    int k = blockIdx.x * 128 + threadIdx.x;   // 0..1151
    int r = blockIdx.y;
    float v;
    if (k < 512)        v = obs [r * 512 + k];
    else if (k < 576)   v = act [r * 64  + (k - 512)];
    else if (k < 1088)  v = nobs[r * 512 + (k - 576)];
    else if (k == 1088) v = rew [r];
    else if (k == 1089) v = term[r];
    else                v = 0.0f;
    g_Xh[(size_t)r * DINP + k] = __float2half_rn(v);
}

// pad w0 [1090,4096] -> fp32 [1152,4096] (repair path)
__global__ void pack_w0f_kernel(const float* __restrict__ w0) {
    int c = blockIdx.x * 128 + threadIdx.x;   // grid.x = 32
    int r = blockIdx.y;                        // 0..1151
    g_W0f[(size_t)r * HDIM + c] = (r < DIN) ? w0[(size_t)r * HDIM + c] : 0.0f;
}

// src [Rv valid rows (K-dim), N] row-major -> dh [N][Kd] transposed, quantized, scaled
__global__ void tsplit_kernel(const float* __restrict__ src, int Rv, int N,
                              __half* __restrict__ dh, int Kd, float scale) {
    __shared__ float t[32][33];
    int k0 = blockIdx.x * 32, n0 = blockIdx.y * 32;
    int tx = threadIdx.x, ty = threadIdx.y;   // (32,8)
#pragma unroll
    for (int i = 0; i < 4; i++) {
        int k = k0 + ty + i * 8;
        t[ty + i * 8][tx] = (k < Rv) ? src[(size_t)k * N + n0 + tx] * scale : 0.0f;
    }
    __syncthreads();
#pragma unroll
    for (int i = 0; i < 4; i++) {
        int n = n0 + ty + i * 8;
        int k = k0 + tx;
        dh[(size_t)n * Kd + k] = __float2half_rn(t[tx][ty + i * 8]);
    }
}

__global__ void prep_et_kernel(const float* __restrict__ E) {
    __shared__ float t[32][33];
    int k0 = blockIdx.x * 32, d0 = blockIdx.y * 32;
    int tx = threadIdx.x, ty = threadIdx.y;
#pragma unroll
    for (int i = 0; i < 4; i++)
        t[ty + i * 8][tx] = E[(size_t)(d0 + ty + i * 8) * KCB + k0 + tx];
    __syncthreads();
#pragma unroll
    for (int i = 0; i < 4; i++)
        g_ET[(size_t)(k0 + ty + i * 8) * DDIM + d0 + tx] = t[tx][ty + i * 8];
}

__global__ void prep_e2_kernel(const float* __restrict__ E) {
    int k = blockIdx.x * 256 + threadIdx.x;
    float s = 0.0f;
    for (int d = 0; d < DDIM; d++) { float v = E[(size_t)d * KCB + k]; s = fmaf(v, v, s); }
    g_e2[k] = s;
}

// ---------------- 1-term fp16 HMMA GEMM: Ah @ Bh^T, fp32 acc ----------------
// 3-stage cp.async pipeline; warp grid 2m x 4n (warp tile 64x32) for 16 indep mma/kk.
#define ST_H   5120                 // halves per matrix tile (128*40)
#define STAGE_H (2 * ST_H)          // Ah | Bh
#define SMEMSZ (3 * STAGE_H * 2)    // bytes (61440)

template<bool RELU, bool WPACK, bool WF32>
__global__ void __launch_bounds__(256, 2)
hmma_kernel(const __half* __restrict__ Ah, const __half* __restrict__ Bh,
            const float* __restrict__ bias,
            __half* __restrict__ Ch, float* __restrict__ Cf,
            int K, int Ntot, float invs) {
    extern __shared__ __align__(16) __half sm[];
    const uint32_t smb = smem_u32(sm);
    const int tid  = threadIdx.x;
    const int wid  = tid >> 5;
    const int lane = tid & 31;
    const int wm   = wid & 1;        // 2 m-warps of 64 rows
    const int wn   = wid >> 1;       // 4 n-warps of 32 cols
    const int m0 = blockIdx.y * 128;
    const int n0 = blockIdx.x * 128;
    const int nkt = K >> 5;

    float acc[4][4][4] = {};         // [mt 0..3][n8 0..3][frag]

    const int lrow = tid >> 2;
    const int lc   = tid & 3;

#define LOADST(kt, s) do {                                                        \
        const size_t gk = (size_t)(kt) * 32 + lc * 8;                             \
        const uint32_t sb = smb + (uint32_t)(s) * (STAGE_H * 2);                  \
        _Pragma("unroll")                                                         \
        for (int i_ = 0; i_ < 2; i_++) {                                          \
            const int r_ = lrow + 64 * i_;                                        \
            const uint32_t so = (uint32_t)(r_ * 40 + lc * 8) * 2;                 \
            cpa16(sb + so,               Ah + (size_t)(m0 + r_) * K + gk);        \
            cpa16(sb + so + ST_H * 2,    Bh + (size_t)(n0 + r_) * K + gk);        \
        }                                                                         \
        CP_COMMIT();                                                              \
    } while (0)

    LOADST(0, 0);
    LOADST(1, 1);

    const int ar  = wm * 64 + (lane & 15);
    const int acx = (lane >> 4) * 8;

    for (int kt = 0; kt < nkt; kt++) {
        const int s = kt % 3;
        if (kt + 1 < nkt) asm volatile("cp.async.wait_group 1;" ::: "memory");
        else              asm volatile("cp.async.wait_group 0;" ::: "memory");
        __syncthreads();   // publishes stage kt; retires compute kt-1 before its stage is overwritten
        if (kt + 2 < nkt) LOADST(kt + 2, (kt + 2) % 3);

        const uint32_t sb = smb + (uint32_t)s * (STAGE_H * 2);
#pragma unroll
        for (int kk = 0; kk < 32; kk += 16) {
            uint32_t ah[4][4];
#pragma unroll
            for (int mt = 0; mt < 4; mt++) {
                const uint32_t ao = (uint32_t)((ar + mt * 16) * 40 + kk + acx) * 2;
                ldsm4(ah[mt], sb + ao);
            }
#pragma unroll
            for (int bt = 0; bt < 2; bt++) {
                const int br = wn * 32 + bt * 16 + (lane & 15);
                const uint32_t bo = (uint32_t)(br * 40 + kk + acx) * 2;
                uint32_t bh[4];
                ldsm4(bh, sb + bo + ST_H * 2);
#pragma unroll
                for (int mt = 0; mt < 4; mt++) {
                    mma16816(acc[mt][2 * bt],     ah[mt], bh[0], bh[2]);
                    mma16816(acc[mt][2 * bt + 1], ah[mt], bh[1], bh[3]);
                }
            }
        }
    }

    const int erow = lane >> 2;
    const int ecol = 2 * (lane & 3);
#pragma unroll
    for (int mt = 0; mt < 4; mt++) {
#pragma unroll
        for (int j = 0; j < 4; j++) {
            const int n = n0 + wn * 32 + j * 8 + ecol;
            float bz0 = 0.f, bz1 = 0.f;
            if (bias) { bz0 = __ldg(&bias[n]); bz1 = __ldg(&bias[n + 1]); }
#pragma unroll
            for (int h = 0; h < 2; h++) {
                const int m = m0 + wm * 64 + mt * 16 + erow + h * 8;
                float v0 = acc[mt][j][2 * h]     * invs + bz0;
                float v1 = acc[mt][j][2 * h + 1] * invs + bz1;
                if (RELU) { v0 = fmaxf(v0, 0.f); v1 = fmaxf(v1, 0.f); }
                const size_t o = (size_t)m * Ntot + n;
                if (WPACK) {
                    *(__half2*)(Ch + o) = __halves2half2(__float2half_rn(v0), __float2half_rn(v1));
                }
                if (WF32) {
                    *(float2*)(Cf + o) = make_float2(v0, v1);
                }
            }
        }
    }
}

// ---------------- fp32 SGEMM (R0-proven, full-K; used for S) ----------------
template<bool RELU>
__global__ __launch_bounds__(256, 2)
void sgemm_kernel(const float* __restrict__ A, const float* __restrict__ B,
                  const float* __restrict__ bias, float* __restrict__ C,
                  int N, int K, const int* limit) {
    if (limit && (int)blockIdx.y * 128 >= min(*limit, RMAX)) return;
    __shared__ float As[8][128];
    __shared__ float Bs[8][128];
    const int tid = threadIdx.x;
    const int bx = blockIdx.x, by = blockIdx.y;
    const float* Ab = A + (size_t)by * 128 * K;
    const float* Bb = B + (size_t)bx * 128;
    const int aRow = tid >> 1, aCol = (tid & 1) * 4;
    const int bRow = tid >> 5, bCol = (tid & 31) * 4;
    const int tx = (tid & 15) * 8, ty = (tid >> 4) * 8;
    float acc[8][8] = {};

    for (int kt = 0; kt < K; kt += 8) {
        float4 av = *reinterpret_cast<const float4*>(Ab + (size_t)aRow * K + kt + aCol);
        float4 bv = *reinterpret_cast<const float4*>(Bb + (size_t)(kt + bRow) * N + bCol);
        As[aCol + 0][aRow] = av.x;
        As[aCol + 1][aRow] = av.y;
        As[aCol + 2][aRow] = av.z;
        As[aCol + 3][aRow] = av.w;
        *reinterpret_cast<float4*>(&Bs[bRow][bCol]) = bv;
        __syncthreads();
#pragma unroll
        for (int kk = 0; kk < 8; kk++) {
            float a[8], b[8];
            *reinterpret_cast<float4*>(&a[0]) = *reinterpret_cast<const float4*>(&As[kk][ty]);
            *reinterpret_cast<float4*>(&a[4]) = *reinterpret_cast<const float4*>(&As[kk][ty + 4]);
            *reinterpret_cast<float4*>(&b[0]) = *reinterpret_cast<const float4*>(&Bs[kk][tx]);
            *reinterpret_cast<float4*>(&b[4]) = *reinterpret_cast<const float4*>(&Bs[kk][tx + 4]);
#pragma unroll
            for (int i = 0; i < 8; i++)
#pragma unroll
                for (int j = 0; j < 8; j++)
                    acc[i][j] = fmaf(a[i], b[j], acc[i][j]);
        }
        __syncthreads();
    }

    float bb[8];
#pragma unroll
    for (int j = 0; j < 8; j++) bb[j] = bias ? bias[bx * 128 + tx + j] : 0.0f;
#pragma unroll
    for (int i = 0; i < 8; i++) {
        float o[8];
#pragma unroll
        for (int j = 0; j < 8; j++) {
            float v = acc[i][j] + bb[j];
            if (RELU) v = fmaxf(v, 0.0f);
            o[j] = v;
        }
        float* Cp = C + (size_t)(by * 128 + ty + i) * N + bx * 128 + tx;
        *reinterpret_cast<float4*>(Cp)     = *reinterpret_cast<float4*>(&o[0]);
        *reinterpret_cast<float4*>(Cp + 4) = *reinterpret_cast<float4*>(&o[4]);
    }
}

// ---------------- fp32 split-K SGEMM (repair; deterministic, 4 slices) ----------------
__global__ __launch_bounds__(256, 2)
void sgemm_splitk_kernel(const float* __restrict__ A, const float* __restrict__ B,
                         int N, int K, const int* limit) {
    if ((int)blockIdx.y * 128 >= min(*limit, RMAX)) return;
    const int Ks = K / NSLICE;
    const int sl = blockIdx.z;
    const int k0 = sl * Ks;
    __shared__ float As[8][128];
    __shared__ float Bs[8][128];
    const int tid = threadIdx.x;
    const int bx = blockIdx.x, by = blockIdx.y;
    const float* Ab = A + (size_t)by * 128 * K + k0;
    const float* Bb = B + (size_t)k0 * N + (size_t)bx * 128;
    const int aRow = tid >> 1, aCol = (tid & 1) * 4;
    const int bRow = tid >> 5, bCol = (tid & 31) * 4;
    const int tx = (tid & 15) * 8, ty = (tid >> 4) * 8;
    float acc[8][8] = {};

    for (int kt = 0; kt < Ks; kt += 8) {
        float4 av = *reinterpret_cast<const float4*>(Ab + (size_t)aRow * K + kt + aCol);
        float4 bv = *reinterpret_cast<const float4*>(Bb + (size_t)(kt + bRow) * N + bCol);
        As[aCol + 0][aRow] = av.x;
        As[aCol + 1][aRow] = av.y;
        As[aCol + 2][aRow] = av.z;
        As[aCol + 3][aRow] = av.w;
        *reinterpret_cast<float4*>(&Bs[bRow][bCol]) = bv;
        __syncthreads();
#pragma unroll
        for (int kk = 0; kk < 8; kk++) {
            float a[8], b[8];
            *reinterpret_cast<float4*>(&a[0]) = *reinterpret_cast<const float4*>(&As[kk][ty]);
            *reinterpret_cast<float4*>(&a[4]) = *reinterpret_cast<const float4*>(&As[kk][ty + 4]);
            *reinterpret_cast<float4*>(&b[0]) = *reinterpret_cast<const float4*>(&Bs[kk][tx]);
            *reinterpret_cast<float4*>(&b[4]) = *reinterpret_cast<const float4*>(&Bs[kk][tx + 4]);
#pragma unroll
            for (int i = 0; i < 8; i++)
#pragma unroll
                for (int j = 0; j < 8; j++)
                    acc[i][j] = fmaf(a[i], b[j], acc[i][j]);
        }
        __syncthreads();
    }
#pragma unroll
    for (int i = 0; i < 8; i++) {
        float* Cp = g_P + ((size_t)sl * RMAX + by * 128 + ty + i) * N + bx * 128 + tx;
        *reinterpret_cast<float4*>(Cp)     = *reinterpret_cast<float4*>(&acc[i][0]);
        *reinterpret_cast<float4*>(Cp + 4) = *reinterpret_cast<float4*>(&acc[i][4]);
    }
}

// deterministic fixed-order reduce of NSLICE partials (+bias)(+relu)
template<bool RELU>
__global__ void reduce_kernel(const float* __restrict__ bias, float* __restrict__ C,
                              int N, const int* limit) {
    const int r = blockIdx.y;
    if (r >= min(*limit, RMAX)) return;
    const int c = blockIdx.x * 256 + threadIdx.x;
    float v = bias ? bias[c] : 0.0f;
#pragma unroll
    for (int s = 0; s < NSLICE; s++)
        v += g_P[((size_t)s * RMAX + r) * N + c];
    if (RELU) v = fmaxf(v, 0.0f);
    C[(size_t)r * N + c] = v;
}

// ---------------- VQ: argmin + ambiguity detection ----------------
__global__ void vq_row_kernel() {
    const int row = blockIdx.x;
    const int tid = threadIdx.x;              // 128
    const float* Sr = g_S + (size_t)row * KCB;

    float best = 3.4e38f; int bi = 0;
    for (int k = tid; k < KCB; k += 128) {
        float dv = fmaf(-2.0f, Sr[k], g_e2[k]);
        if (dv < best) { best = dv; bi = k; }
    }
    __shared__ float sv[128];
    __shared__ int   si[128];
    sv[tid] = best; si[tid] = bi;
    __syncthreads();
    for (int s = 64; s > 0; s >>= 1) {
        if (tid < s) {
            float ov = sv[tid + s]; int oi = si[tid + s];
            if (ov < sv[tid] || (ov == sv[tid] && oi < si[tid])) { sv[tid] = ov; si[tid] = oi; }
        }
        __syncthreads();
    }
    const int idx = si[0];
    const float d1 = sv[0];
    __syncthreads();

    float b2 = 3.4e38f;
    for (int k = tid; k < KCB; k += 128) {
        if (k == idx) continue;
        float dv = fmaf(-2.0f, Sr[k], g_e2[k]);
        b2 = fminf(b2, dv);
    }
    sv[tid] = b2;
    __syncthreads();
    for (int s = 64; s > 0; s >>= 1) {
        if (tid < s) sv[tid] = fminf(sv[tid], sv[tid + s]);
        __syncthreads();
    }

    if (tid == 0) {
        g_idx[row] = idx;
        if (sv[0] - d1 < ARG_TH) {
            int slot = atomicAdd(&g_nfix, 1);
            if (slot < RMAX) g_fixlist[slot] = row;
        }
    }
}

// gather padded fp32 X rows for the repair batch
__global__ void gather_fix_kernel(const float* __restrict__ obs, const float* __restrict__ act,
                                  const float* __restrict__ nobs, const float* __restrict__ rew,
                                  const float* __restrict__ term) {
    const int i = blockIdx.y;
    if (i >= min(g_nfix, RMAX)) return;
    const int r = g_fixlist[i];
    const int k = blockIdx.x * 128 + threadIdx.x;
    float v;
    if (k < 512)        v = obs [r * 512 + k];
    else if (k < 576)   v = act [r * 64  + (k - 512)];
    else if (k < 1088)  v = nobs[r * 512 + (k - 576)];
    else if (k == 1088) v = rew [r];
    else if (k == 1089) v = term[r];
    else                v = 0.0f;
    g_Xa[(size_t)i * DINP + k] = v;
}

// exact fp32 argmin for repaired rows
__global__ void repair_argmin_kernel() {
    const int i = blockIdx.x;
    if (i >= min(g_nfix, RMAX)) return;
    const int tid = threadIdx.x;              // 128
    __shared__ float zs[DDIM];
    const float* za = g_Za + (size_t)i * DDIM;
    for (int d = tid; d < DDIM; d += 128) zs[d] = za[d];
    __syncthreads();

    float best = 3.4e38f; int bi = 0;
    for (int k = tid; k < KCB; k += 128) {
        const float* e = g_ET + (size_t)k * DDIM;
        float dot = 0.0f;
        for (int d = 0; d < DDIM; d++) dot = fmaf(zs[d], e[d], dot);
        float dv = fmaf(-2.0f, dot, g_e2[k]);
        if (dv < best) { best = dv; bi = k; }
    }
    __shared__ float sv[128];
    __shared__ int   si[128];
    sv[tid] = best; si[tid] = bi;
    __syncthreads();
    for (int s = 64; s > 0; s >>= 1) {
        if (tid < s) {
            float ov = sv[tid + s]; int oi = si[tid + s];
            if (ov < sv[tid] || (ov == sv[tid] && oi < si[tid])) { sv[tid] = ov; si[tid] = oi; }
        }
        __syncthreads();
    }
    if (tid == 0) g_idx[g_fixlist[i]] = si[0];
}

// counts + q gather + rowloss using FINAL indices
__global__ void vq_finish_kernel(float* __restrict__ qout) {
    const int row = blockIdx.x;
    const int tid = threadIdx.x;              // 128
    const int idx = g_idx[row];
    if (tid == 0) atomicAdd(&g_counts[idx], 1.0f);

    const float* e = g_ET + (size_t)idx * DDIM;
    const float* z = g_Z  + (size_t)row * DDIM;
    float ls = 0.0f;
    for (int d = tid; d < DDIM; d += 128) {
        float q = e[d], zz = z[d];
        qout[(size_t)row * DDIM + d] = q;
        float t = q - zz;
        ls = fmaf(t, t, ls);
    }
    __shared__ float sv[128];
    sv[tid] = ls;
    __syncthreads();
    for (int s = 64; s > 0; s >>= 1) { if (tid < s) sv[tid] += sv[tid + s]; __syncthreads(); }
    if (tid == 0) g_rowloss[row] = sv[0];
}

__global__ void vq_stats_kernel(const float* __restrict__ ema_cs, float* __restrict__ out) {
    const int k = threadIdx.x;
    __shared__ float red[512];
    __shared__ float shn, shent;
    float cnt = g_counts[k];
    float cs  = 0.99f * ema_cs[k] + 0.01f * cnt;
    red[k] = cs; __syncthreads();
    for (int s = 256; s > 0; s >>= 1) { if (k < s) red[k] += red[k + s]; __syncthreads(); }
    if (k == 0) shn = red[0];
    __syncthreads();
    float p = cnt * (1.0f / 16384.0f);
    red[k] = p * logf(p + 1e-10f);
    __syncthreads();
    for (int s = 256; s > 0; s >>= 1) { if (k < s) red[k] += red[k + s]; __syncthreads(); }
    if (k == 0) shent = red[0];
    __syncthreads();
    float ls = 0.0f;
    for (int r = k; r < BATCH; r += 512) ls += g_rowloss[r];
    red[k] = ls; __syncthreads();
    for (int s = 256; s > 0; s >>= 1) { if (k < s) red[k] += red[k + s]; __syncthreads(); }
    float n   = shn;
    float csn = (cs + 1e-5f) / (n + 512.0f * 1e-5f) * n;
    g_cs[k] = csn;
    out[OUT_CS + k] = csn;
    if (k == 0) {
        out[OUT_LOSS] = 0.25f * red[0] / 16777216.0f;
        out[OUT_PERP] = expf(-shent);
    }
}

__global__ void vq_dw_kernel() {
    const int k = blockIdx.x;
    const int tid = threadIdx.x;
    float a0 = 0.f, a1 = 0.f, a2 = 0.f, a3 = 0.f;
    __shared__ unsigned smask[8];
    for (int b0 = 0; b0 < BATCH; b0 += 256) {
        int mi = g_idx[b0 + tid];
        unsigned m = __ballot_sync(0xffffffffu, mi == k);
        if ((tid & 31) == 0) smask[tid >> 5] = m;
        __syncthreads();
#pragma unroll
        for (int w = 0; w < 8; w++) {
            unsigned mm = smask[w];
            while (mm) {
                int bit = __ffs(mm) - 1;
                mm &= mm - 1;
                const float* z = g_Z + (size_t)(b0 + w * 32 + bit) * DDIM;
                a0 += z[tid]; a1 += z[tid + 256]; a2 += z[tid + 512]; a3 += z[tid + 768];
            }
        }
        __syncthreads();
    }
    g_dwT[(size_t)k * DDIM + tid]       = a0;
    g_dwT[(size_t)k * DDIM + tid + 256] = a1;
    g_dwT[(size_t)k * DDIM + tid + 512] = a2;
    g_dwT[(size_t)k * DDIM + tid + 768] = a3;
}

__global__ void emb_out_kernel(const float* __restrict__ ema_dw, float* __restrict__ out) {
    __shared__ float t[32][33];
    int k0 = blockIdx.x * 32, d0 = blockIdx.y * 32;
    int tx = threadIdx.x, ty = threadIdx.y;
#pragma unroll
    for (int i = 0; i < 4; i++)
        t[ty + i * 8][tx] = g_dwT[(size_t)(k0 + ty + i * 8) * DDIM + d0 + tx];
    __syncthreads();
#pragma unroll
    for (int i = 0; i < 4; i++) {
        int d = d0 + ty + i * 8;
        int k = k0 + tx;
        float v = 0.99f * ema_dw[(size_t)d * KCB + k] + 0.01f * t[tx][ty + i * 8];
        out[OUT_EMB + (size_t)d * KCB + k] = v / g_cs[k];
    }
}

// ---------------- launcher ----------------
extern "C" void kernel_launch(void* const* d_in, const int* in_sizes, int n_in,
                              void* d_out, int out_size) {
    const float* obs    = (const float*)d_in[0];
    const float* action = (const float*)d_in[1];
    const float* nobs   = (const float*)d_in[2];
    const float* rew    = (const float*)d_in[3];
    const float* term   = (const float*)d_in[4];
    const float* w0 = (const float*)d_in[5];
    const float* b0 = (const float*)d_in[6];
    const float* w1 = (const float*)d_in[7];
    const float* b1 = (const float*)d_in[8];
    const float* w2 = (const float*)d_in[9];
    const float* b2 = (const float*)d_in[10];
    const float* w3 = (const float*)d_in[11];
    const float* b3 = (const float*)d_in[12];
    const float* wl = (const float*)d_in[13];
    const float* bl = (const float*)d_in[14];
    const float* emb    = (const float*)d_in[15];
    const float* ema_cs = (const float*)d_in[16];
    const float* ema_dw = (const float*)d_in[17];
    float* out = (float*)d_out;

    __half *pXh, *pW0h, *pW1h, *pW2h, *pW3h, *pWLh, *pA1h, *pA2h;
    float *pZ, *pS, *pW0f, *pXa, *pHa, *pHb, *pZa;
    int *pNfix;
    cudaGetSymbolAddress((void**)&pXh,  g_Xh);
    cudaGetSymbolAddress((void**)&pW0h, g_W0h);
    cudaGetSymbolAddress((void**)&pW1h, g_W1h);
    cudaGetSymbolAddress((void**)&pW2h, g_W2h);
    cudaGetSymbolAddress((void**)&pW3h, g_W3h);
    cudaGetSymbolAddress((void**)&pWLh, g_WLh);
    cudaGetSymbolAddress((void**)&pA1h, g_A1h);
    cudaGetSymbolAddress((void**)&pA2h, g_A2h);
    cudaGetSymbolAddress((void**)&pZ,   g_Z);
    cudaGetSymbolAddress((void**)&pS,   g_S);
    cudaGetSymbolAddress((void**)&pW0f, g_W0f);
    cudaGetSymbolAddress((void**)&pXa,  g_Xa);
    cudaGetSymbolAddress((void**)&pHa,  g_Ha);
    cudaGetSymbolAddress((void**)&pHb,  g_Hb);
    cudaGetSymbolAddress((void**)&pZa,  g_Za);
    cudaGetSymbolAddress((void**)&pNfix, g_nfix);

    cudaFuncSetAttribute(hmma_kernel<true,  true,  false>, cudaFuncAttributeMaxDynamicSharedMemorySize, SMEMSZ);
    cudaFuncSetAttribute(hmma_kernel<false, false, true >, cudaFuncAttributeMaxDynamicSharedMemorySize, SMEMSZ);

    const float is256 = 1.0f / 256.0f;

    zero_counts_kernel<<<2, 256>>>();
    pack_x0_kernel<<<dim3(9, BATCH), 128>>>(obs, action, nobs, rew, term);
    pack_w0f_kernel<<<dim3(32, DINP), 128>>>(w0);
    tsplit_kernel<<<dim3(DINP/32, HDIM/32), dim3(32, 8)>>>(w0, DIN,  HDIM, pW0h, DINP, 256.0f);
    tsplit_kernel<<<dim3(HDIM/32, HDIM/32), dim3(32, 8)>>>(w1, HDIM, HDIM, pW1h, HDIM, 256.0f);
    tsplit_kernel<<<dim3(HDIM/32, HDIM/32), dim3(32, 8)>>>(w2, HDIM, HDIM, pW2h, HDIM, 256.0f);
    tsplit_kernel<<<dim3(HDIM/32, HDIM/32), dim3(32, 8)>>>(w3, HDIM, HDIM, pW3h, HDIM, 256.0f);
    tsplit_kernel<<<dim3(HDIM/32, DDIM/32), dim3(32, 8)>>>(wl, HDIM, DDIM, pWLh, HDIM, 256.0f);
    prep_et_kernel<<<dim3(KCB/32, DDIM/32), dim3(32, 8)>>>(emb);
    prep_e2_kernel<<<2, 256>>>(emb);

    // MLP encoder (1-term fp16 HMMA, 64x32 warp tiles); WL layer emits fp32 z
    hmma_kernel<true,  true,  false><<<dim3(HDIM/128, BATCH/128), 256, SMEMSZ>>>(pXh,  pW0h, b0, pA1h, nullptr, DINP, HDIM, is256);
    hmma_kernel<true,  true,  false><<<dim3(HDIM/128, BATCH/128), 256, SMEMSZ>>>(pA1h, pW1h, b1, pA2h, nullptr, HDIM, HDIM, is256);
    hmma_kernel<true,  true,  false><<<dim3(HDIM/128, BATCH/128), 256, SMEMSZ>>>(pA2h, pW2h, b2, pA1h, nullptr, HDIM, HDIM, is256);
    hmma_kernel<true,  true,  false><<<dim3(HDIM/128, BATCH/128), 256, SMEMSZ>>>(pA1h, pW3h, b3, pA2h, nullptr, HDIM, HDIM, is256);
    hmma_kernel<false, false, true ><<<dim3(DDIM/128, BATCH/128), 256, SMEMSZ>>>(pA2h, pWLh, bl, nullptr, pZ, HDIM, DDIM, is256);

    // S = z @ embeddings in fp32
    sgemm_kernel<false><<<dim3(KCB/128, BATCH/128), 256>>>(pZ, emb, nullptr, pS, KCB, DDIM, nullptr);

    // argmin + ambiguity flagging
    vq_row_kernel<<<BATCH, 128>>>();

    // exact fp32 repair for ambiguous rows (split-K4 for low latency; no-ops when none)
    gather_fix_kernel<<<dim3(9, RMAX), 128>>>(obs, action, nobs, rew, term);
    sgemm_splitk_kernel<<<dim3(HDIM/128, RMAX/128, NSLICE), 256>>>(pXa, pW0f, HDIM, DINP, pNfix);
    reduce_kernel<true ><<<dim3(HDIM/256, RMAX), 256>>>(b0, pHa, HDIM, pNfix);
    sgemm_splitk_kernel<<<dim3(HDIM/128, RMAX/128, NSLICE), 256>>>(pHa, w1, HDIM, HDIM, pNfix);
    reduce_kernel<true ><<<dim3(HDIM/256, RMAX), 256>>>(b1, pHb, HDIM, pNfix);
    sgemm_splitk_kernel<<<dim3(HDIM/128, RMAX/128, NSLICE), 256>>>(pHb, w2, HDIM, HDIM, pNfix);
    reduce_kernel<true ><<<dim3(HDIM/256, RMAX), 256>>>(b2, pHa, HDIM, pNfix);
    sgemm_splitk_kernel<<<dim3(HDIM/128, RMAX/128, NSLICE), 256>>>(pHa, w3, HDIM, HDIM, pNfix);
    reduce_kernel<true ><<<dim3(HDIM/256, RMAX), 256>>>(b3, pHb, HDIM, pNfix);
    sgemm_splitk_kernel<<<dim3(DDIM/128, RMAX/128, NSLICE), 256>>>(pHb, wl, DDIM, HDIM, pNfix);
    reduce_kernel<false><<<dim3(DDIM/256, RMAX), 256>>>(bl, pZa, DDIM, pNfix);
    repair_argmin_kernel<<<RMAX, 128>>>();

    // finish VQ with final indices
    vq_finish_kernel<<<BATCH, 128>>>(out);
    vq_stats_kernel<<<1, 512>>>(ema_cs, out);
    vq_dw_kernel<<<KCB, 256>>>();
    emb_out_kernel<<<dim3(KCB/32, DDIM/32), dim3(32, 8)>>>(ema_dw, out);
}

// round 16
// speedup vs baseline: 1.0639x; 1.0639x over previous
#include <cuda_runtime.h>
#include <cuda_fp16.h>
#include <math.h>
#include <stdint.h>

// ---------------- problem constants ----------------
#define BATCH 16384
#define HDIM  4096
#define DDIM  1024
#define KCB   512
#define DIN   1090
#define DINP  1152
#define RMAX  2048
#define ARG_TH 0.30f
#define NSLICE 8

#define OUT_Q    0
#define OUT_LOSS 16777216
#define OUT_PERP 16777217
#define OUT_EMB  16777218
#define OUT_CS   17301506

// ---------------- scratch (device globals; no allocation) ----------------
__device__ __half g_Xh [(size_t)BATCH * DINP];
__device__ __half g_W0h[(size_t)HDIM * DINP];
__device__ __half g_W1h[(size_t)HDIM * HDIM];
__device__ __half g_W2h[(size_t)HDIM * HDIM];
__device__ __half g_W3h[(size_t)HDIM * HDIM];
__device__ __half g_WLh[(size_t)DDIM * HDIM];
__device__ __half g_A1h[(size_t)BATCH * HDIM];
__device__ __half g_A2h[(size_t)BATCH * HDIM];
__device__ float  g_Z  [(size_t)BATCH * DDIM];
__device__ float  g_S  [(size_t)BATCH * KCB];
__device__ float  g_ET [(size_t)KCB * DDIM];
__device__ float  g_e2 [KCB];
__device__ int    g_idx[BATCH];
__device__ float  g_counts[KCB];
__device__ float  g_cs [KCB];
__device__ float  g_rowloss[BATCH];
__device__ float  g_dwT[(size_t)KCB * DDIM];
// repair path
__device__ int    g_nfix;
__device__ int    g_fixlist[RMAX];
__device__ float  g_W0f[(size_t)DINP * HDIM];
__device__ float  g_Xa [(size_t)RMAX * DINP];
__device__ float  g_Ha [(size_t)RMAX * HDIM];
__device__ float  g_Hb [(size_t)RMAX * HDIM];
__device__ float  g_Za [(size_t)RMAX * DDIM];
__device__ float  g_P  [(size_t)NSLICE * RMAX * HDIM];   // split-K partials

// ---------------- PTX helpers (all baseline sm_80-class) ----------------
__device__ __forceinline__ uint32_t smem_u32(const void* p) {
    uint32_t a;
    asm("{ .reg .u64 t; cvta.to.shared.u64 t, %1; cvt.u32.u64 %0, t; }" : "=r"(a) : "l"(p));
    return a;
}
__device__ __forceinline__ void cpa16(uint32_t s, const void* g) {
    asm volatile("cp.async.cg.shared.global [%0], [%1], 16;" :: "r"(s), "l"(g));
}
#define CP_COMMIT() asm volatile("cp.async.commit_group;" ::: "memory")

__device__ __forceinline__ void ldsm4(uint32_t* r, uint32_t a) {
    asm volatile("ldmatrix.sync.aligned.m8n8.x4.shared.b16 {%0,%1,%2,%3}, [%4];"
                 : "=r"(r[0]), "=r"(r[1]), "=r"(r[2]), "=r"(r[3]) : "r"(a));
}
__device__ __forceinline__ void mma16816(float* c, const uint32_t* a, uint32_t b0, uint32_t b1) {
    asm volatile("mma.sync.aligned.m16n8k16.row.col.f32.f16.f16.f32 "
                 "{%0,%1,%2,%3}, {%4,%5,%6,%7}, {%8,%9}, {%0,%1,%2,%3};"
                 : "+f"(c[0]), "+f"(c[1]), "+f"(c[2]), "+f"(c[3])
                 : "r"(a[0]), "r"(a[1]), "r"(a[2]), "r"(a[3]), "r"(b0), "r"(b1));
}

// ---------------- prep kernels ----------------
__global__ void zero_counts_kernel() {
    g_counts[blockIdx.x * 256 + threadIdx.x] = 0.0f;
    if (blockIdx.x == 0 && threadIdx.x == 0) g_nfix = 0;
}

__global__ void pack_x0_kernel(const float* __restrict__ obs, const float* __restrict__ act,
                               const float* __restrict__ nobs, const float* __restrict__ rew,
                               const float* __restrict__ term) {
    int k = blockIdx.x * 128 + threadIdx.x;   // 0..1151
    int r = blockIdx.y;
    float v;
    if (k < 512)        v = obs [r * 512 + k];
    else if (k < 576)   v = act [r * 64  + (k - 512)];
    else if (k < 1088)  v = nobs[r * 512 + (k - 576)];
    else if (k == 1088) v = rew [r];
    else if (k == 1089) v = term[r];
    else                v = 0.0f;
    g_Xh[(size_t)r * DINP + k] = __float2half_rn(v);
}

// pad w0 [1090,4096] -> fp32 [1152,4096] (repair path)
__global__ void pack_w0f_kernel(const float* __restrict__ w0) {
    int c = blockIdx.x * 128 + threadIdx.x;   // grid.x = 32
    int r = blockIdx.y;                        // 0..1151
    g_W0f[(size_t)r * HDIM + c] = (r < DIN) ? w0[(size_t)r * HDIM + c] : 0.0f;
}

// src [Rv valid rows (K-dim), N] row-major -> dh [N][Kd] transposed, quantized, scaled
__global__ void tsplit_kernel(const float* __restrict__ src, int Rv, int N,
                              __half* __restrict__ dh, int Kd, float scale) {
    __shared__ float t[32][33];
    int k0 = blockIdx.x * 32, n0 = blockIdx.y * 32;
    int tx = threadIdx.x, ty = threadIdx.y;   // (32,8)
#pragma unroll
    for (int i = 0; i < 4; i++) {
        int k = k0 + ty + i * 8;
        t[ty + i * 8][tx] = (k < Rv) ? src[(size_t)k * N + n0 + tx] * scale : 0.0f;
    }
    __syncthreads();
#pragma unroll
    for (int i = 0; i < 4; i++) {
        int n = n0 + ty + i * 8;
        int k = k0 + tx;
        dh[(size_t)n * Kd + k] = __float2half_rn(t[tx][ty + i * 8]);
    }
}

__global__ void prep_et_kernel(const float* __restrict__ E) {
    __shared__ float t[32][33];
    int k0 = blockIdx.x * 32, d0 = blockIdx.y * 32;
    int tx = threadIdx.x, ty = threadIdx.y;
#pragma unroll
    for (int i = 0; i < 4; i++)
        t[ty + i * 8][tx] = E[(size_t)(d0 + ty + i * 8) * KCB + k0 + tx];
    __syncthreads();
#pragma unroll
    for (int i = 0; i < 4; i++)
        g_ET[(size_t)(k0 + ty + i * 8) * DDIM + d0 + tx] = t[tx][ty + i * 8];
}

__global__ void prep_e2_kernel(const float* __restrict__ E) {
    int k = blockIdx.x * 256 + threadIdx.x;
    float s = 0.0f;
    for (int d = 0; d < DDIM; d++) { float v = E[(size_t)d * KCB + k]; s = fmaf(v, v, s); }
    g_e2[k] = s;
}

// ---------------- 1-term fp16 HMMA GEMM: Ah @ Bh^T, fp32 acc ----------------
// 3-stage cp.async pipeline, single barrier per K-step, warp grid 4m x 2n.
#define ST_H   5120                 // halves per matrix tile (128*40)
#define STAGE_H (2 * ST_H)          // Ah | Bh
#define SMEMSZ (3 * STAGE_H * 2)    // bytes (61440)

template<bool RELU, bool WPACK, bool WF32>
__global__ void __launch_bounds__(256, 2)
hmma_kernel(const __half* __restrict__ Ah, const __half* __restrict__ Bh,
            const float* __restrict__ bias,
            __half* __restrict__ Ch, float* __restrict__ Cf,
            int K, int Ntot, float invs) {
    extern __shared__ __align__(16) __half sm[];
    const uint32_t smb = smem_u32(sm);
    const int tid  = threadIdx.x;
    const int wid  = tid >> 5;
    const int lane = tid & 31;
    const int wm   = wid & 3;
    const int wn   = wid >> 2;
    const int m0 = blockIdx.y * 128;
    const int n0 = blockIdx.x * 128;
    const int nkt = K >> 5;

    float acc[2][8][4] = {};

    const int lrow = tid >> 2;
    const int lc   = tid & 3;

#define LOADST(kt, s) do {                                                        \
        const size_t gk = (size_t)(kt) * 32 + lc * 8;                             \
        const uint32_t sb = smb + (uint32_t)(s) * (STAGE_H * 2);                  \
        _Pragma("unroll")                                                         \
        for (int i_ = 0; i_ < 2; i_++) {                                          \
            const int r_ = lrow + 64 * i_;                                        \
            const uint32_t so = (uint32_t)(r_ * 40 + lc * 8) * 2;                 \
            cpa16(sb + so,               Ah + (size_t)(m0 + r_) * K + gk);        \
            cpa16(sb + so + ST_H * 2,    Bh + (size_t)(n0 + r_) * K + gk);        \
        }                                                                         \
        CP_COMMIT();                                                              \
    } while (0)

    LOADST(0, 0);
    LOADST(1, 1);

    const int ar  = wm * 32 + (lane & 15);
    const int acx = (lane >> 4) * 8;

    for (int kt = 0; kt < nkt; kt++) {
        const int s = kt % 3;
        if (kt + 1 < nkt) asm volatile("cp.async.wait_group 1;" ::: "memory");
        else              asm volatile("cp.async.wait_group 0;" ::: "memory");
        __syncthreads();
        if (kt + 2 < nkt) LOADST(kt + 2, (kt + 2) % 3);

        const uint32_t sb = smb + (uint32_t)s * (STAGE_H * 2);
#pragma unroll
        for (int kk = 0; kk < 32; kk += 16) {
            uint32_t ah[2][4];
#pragma unroll
            for (int mt = 0; mt < 2; mt++) {
                const uint32_t ao = (uint32_t)((ar + mt * 16) * 40 + kk + acx) * 2;
                ldsm4(ah[mt], sb + ao);
            }
#pragma unroll
            for (int nt = 0; nt < 4; nt++) {
                const int br = wn * 64 + nt * 16 + (lane & 15);
                const uint32_t bo = (uint32_t)(br * 40 + kk + acx) * 2;
                uint32_t bh[4];
                ldsm4(bh, sb + bo + ST_H * 2);
#pragma unroll
                for (int mt = 0; mt < 2; mt++) {
                    mma16816(acc[mt][2 * nt],     ah[mt], bh[0], bh[2]);
                    mma16816(acc[mt][2 * nt + 1], ah[mt], bh[1], bh[3]);
                }
            }
        }
    }

    const int erow = lane >> 2;
    const int ecol = 2 * (lane & 3);
#pragma unroll
    for (int mt = 0; mt < 2; mt++) {
#pragma unroll
        for (int j = 0; j < 8; j++) {
            const int n = n0 + wn * 64 + j * 8 + ecol;
            float bz0 = 0.f, bz1 = 0.f;
            if (bias) { bz0 = __ldg(&bias[n]); bz1 = __ldg(&bias[n + 1]); }
#pragma unroll
            for (int h = 0; h < 2; h++) {
                const int m = m0 + wm * 32 + mt * 16 + erow + h * 8;
                float v0 = acc[mt][j][2 * h]     * invs + bz0;
                float v1 = acc[mt][j][2 * h + 1] * invs + bz1;
                if (RELU) { v0 = fmaxf(v0, 0.f); v1 = fmaxf(v1, 0.f); }
                const size_t o = (size_t)m * Ntot + n;
                if (WPACK) {
                    *(__half2*)(Ch + o) = __halves2half2(__float2half_rn(v0), __float2half_rn(v1));
                }
                if (WF32) {
                    *(float2*)(Cf + o) = make_float2(v0, v1);
                }
            }
        }
    }
}

// ---------------- fp32 SGEMM (R0-proven, full-K; used for S) ----------------
template<bool RELU>
__global__ __launch_bounds__(256, 2)
void sgemm_kernel(const float* __restrict__ A, const float* __restrict__ B,
                  const float* __restrict__ bias, float* __restrict__ C,
                  int N, int K, const int* limit) {
    if (limit && (int)blockIdx.y * 128 >= min(*limit, RMAX)) return;
    __shared__ float As[8][128];
    __shared__ float Bs[8][128];
    const int tid = threadIdx.x;
    const int bx = blockIdx.x, by = blockIdx.y;
    const float* Ab = A + (size_t)by * 128 * K;
    const float* Bb = B + (size_t)bx * 128;
    const int aRow = tid >> 1, aCol = (tid & 1) * 4;
    const int bRow = tid >> 5, bCol = (tid & 31) * 4;
    const int tx = (tid & 15) * 8, ty = (tid >> 4) * 8;
    float acc[8][8] = {};

    for (int kt = 0; kt < K; kt += 8) {
        float4 av = *reinterpret_cast<const float4*>(Ab + (size_t)aRow * K + kt + aCol);
        float4 bv = *reinterpret_cast<const float4*>(Bb + (size_t)(kt + bRow) * N + bCol);
        As[aCol + 0][aRow] = av.x;
        As[aCol + 1][aRow] = av.y;
        As[aCol + 2][aRow] = av.z;
        As[aCol + 3][aRow] = av.w;
        *reinterpret_cast<float4*>(&Bs[bRow][bCol]) = bv;
        __syncthreads();
#pragma unroll
        for (int kk = 0; kk < 8; kk++) {
            float a[8], b[8];
            *reinterpret_cast<float4*>(&a[0]) = *reinterpret_cast<const float4*>(&As[kk][ty]);
            *reinterpret_cast<float4*>(&a[4]) = *reinterpret_cast<const float4*>(&As[kk][ty + 4]);
            *reinterpret_cast<float4*>(&b[0]) = *reinterpret_cast<const float4*>(&Bs[kk][tx]);
            *reinterpret_cast<float4*>(&b[4]) = *reinterpret_cast<const float4*>(&Bs[kk][tx + 4]);
#pragma unroll
            for (int i = 0; i < 8; i++)
#pragma unroll
                for (int j = 0; j < 8; j++)
                    acc[i][j] = fmaf(a[i], b[j], acc[i][j]);
        }
        __syncthreads();
    }

    float bb[8];
#pragma unroll
    for (int j = 0; j < 8; j++) bb[j] = bias ? bias[bx * 128 + tx + j] : 0.0f;
#pragma unroll
    for (int i = 0; i < 8; i++) {
        float o[8];
#pragma unroll
        for (int j = 0; j < 8; j++) {
            float v = acc[i][j] + bb[j];
            if (RELU) v = fmaxf(v, 0.0f);
            o[j] = v;
        }
        float* Cp = C + (size_t)(by * 128 + ty + i) * N + bx * 128 + tx;
        *reinterpret_cast<float4*>(Cp)     = *reinterpret_cast<float4*>(&o[0]);
        *reinterpret_cast<float4*>(Cp + 4) = *reinterpret_cast<float4*>(&o[4]);
    }
}

// ---------------- fp32 split-K SGEMM (repair; deterministic, NSLICE slices) ----------------
__global__ __launch_bounds__(256, 2)
void sgemm_splitk_kernel(const float* __restrict__ A, const float* __restrict__ B,
                         int N, int K, const int* limit) {
    if ((int)blockIdx.y * 128 >= min(*limit, RMAX)) return;
    const int Ks = K / NSLICE;
    const int sl = blockIdx.z;
    const int k0 = sl * Ks;
    __shared__ float As[8][128];
    __shared__ float Bs[8][128];
    const int tid = threadIdx.x;
    const int bx = blockIdx.x, by = blockIdx.y;
    const float* Ab = A + (size_t)by * 128 * K + k0;
    const float* Bb = B + (size_t)k0 * N + (size_t)bx * 128;
    const int aRow = tid >> 1, aCol = (tid & 1) * 4;
    const int bRow = tid >> 5, bCol = (tid & 31) * 4;
    const int tx = (tid & 15) * 8, ty = (tid >> 4) * 8;
    float acc[8][8] = {};

    for (int kt = 0; kt < Ks; kt += 8) {
        float4 av = *reinterpret_cast<const float4*>(Ab + (size_t)aRow * K + kt + aCol);
        float4 bv = *reinterpret_cast<const float4*>(Bb + (size_t)(kt + bRow) * N + bCol);
        As[aCol + 0][aRow] = av.x;
        As[aCol + 1][aRow] = av.y;
        As[aCol + 2][aRow] = av.z;
        As[aCol + 3][aRow] = av.w;
        *reinterpret_cast<float4*>(&Bs[bRow][bCol]) = bv;
        __syncthreads();
#pragma unroll
        for (int kk = 0; kk < 8; kk++) {
            float a[8], b[8];
            *reinterpret_cast<float4*>(&a[0]) = *reinterpret_cast<const float4*>(&As[kk][ty]);
            *reinterpret_cast<float4*>(&a[4]) = *reinterpret_cast<const float4*>(&As[kk][ty + 4]);
            *reinterpret_cast<float4*>(&b[0]) = *reinterpret_cast<const float4*>(&Bs[kk][tx]);
            *reinterpret_cast<float4*>(&b[4]) = *reinterpret_cast<const float4*>(&Bs[kk][tx + 4]);
#pragma unroll
            for (int i = 0; i < 8; i++)
#pragma unroll
                for (int j = 0; j < 8; j++)
                    acc[i][j] = fmaf(a[i], b[j], acc[i][j]);
        }
        __syncthreads();
    }
#pragma unroll
    for (int i = 0; i < 8; i++) {
        float* Cp = g_P + ((size_t)sl * RMAX + by * 128 + ty + i) * N + bx * 128 + tx;
        *reinterpret_cast<float4*>(Cp)     = *reinterpret_cast<float4*>(&acc[i][0]);
        *reinterpret_cast<float4*>(Cp + 4) = *reinterpret_cast<float4*>(&acc[i][4]);
    }
}

// deterministic fixed-order reduce of NSLICE partials (+bias)(+relu)
template<bool RELU>
__global__ void reduce_kernel(const float* __restrict__ bias, float* __restrict__ C,
                              int N, const int* limit) {
    const int r = blockIdx.y;
    if (r >= min(*limit, RMAX)) return;
    const int c = blockIdx.x * 256 + threadIdx.x;
    float v = bias ? bias[c] : 0.0f;
#pragma unroll
    for (int s = 0; s < NSLICE; s++)
        v += g_P[((size_t)s * RMAX + r) * N + c];
    if (RELU) v = fmaxf(v, 0.0f);
    C[(size_t)r * N + c] = v;
}

// ---------------- VQ: argmin + ambiguity detection ----------------
__global__ void vq_row_kernel() {
    const int row = blockIdx.x;
    const int tid = threadIdx.x;              // 128
    const float* Sr = g_S + (size_t)row * KCB;

    float best = 3.4e38f; int bi = 0;
    for (int k = tid; k < KCB; k += 128) {
        float dv = fmaf(-2.0f, Sr[k], g_e2[k]);
        if (dv < best) { best = dv; bi = k; }
    }
    __shared__ float sv[128];
    __shared__ int   si[128];
    sv[tid] = best; si[tid] = bi;
    __syncthreads();
    for (int s = 64; s > 0; s >>= 1) {
        if (tid < s) {
            float ov = sv[tid + s]; int oi = si[tid + s];
            if (ov < sv[tid] || (ov == sv[tid] && oi < si[tid])) { sv[tid] = ov; si[tid] = oi; }
        }
        __syncthreads();
    }
    const int idx = si[0];
    const float d1 = sv[0];
    __syncthreads();

    float b2 = 3.4e38f;
    for (int k = tid; k < KCB; k += 128) {
        if (k == idx) continue;
        float dv = fmaf(-2.0f, Sr[k], g_e2[k]);
        b2 = fminf(b2, dv);
    }
    sv[tid] = b2;
    __syncthreads();
    for (int s = 64; s > 0; s >>= 1) {
        if (tid < s) sv[tid] = fminf(sv[tid], sv[tid + s]);
        __syncthreads();
    }

    if (tid == 0) {
        g_idx[row] = idx;
        if (sv[0] - d1 < ARG_TH) {
            int slot = atomicAdd(&g_nfix, 1);
            if (slot < RMAX) g_fixlist[slot] = row;
        }
    }
}

// gather padded fp32 X rows for the repair batch
__global__ void gather_fix_kernel(const float* __restrict__ obs, const float* __restrict__ act,
                                  const float* __restrict__ nobs, const float* __restrict__ rew,
                                  const float* __restrict__ term) {
    const int i = blockIdx.y;
    if (i >= min(g_nfix, RMAX)) return;
    const int r = g_fixlist[i];
    const int k = blockIdx.x * 128 + threadIdx.x;
    float v;
    if (k < 512)        v = obs [r * 512 + k];
    else if (k < 576)   v = act [r * 64  + (k - 512)];
    else if (k < 1088)  v = nobs[r * 512 + (k - 576)];
    else if (k == 1088) v = rew [r];
    else if (k == 1089) v = term[r];
    else                v = 0.0f;
    g_Xa[(size_t)i * DINP + k] = v;
}

// exact fp32 argmin for repaired rows
__global__ void repair_argmin_kernel() {
    const int i = blockIdx.x;
    if (i >= min(g_nfix, RMAX)) return;
    const int tid = threadIdx.x;              // 128
    __shared__ float zs[DDIM];
    const float* za = g_Za + (size_t)i * DDIM;
    for (int d = tid; d < DDIM; d += 128) zs[d] = za[d];
    __syncthreads();

    float best = 3.4e38f; int bi = 0;
    for (int k = tid; k < KCB; k += 128) {
        const float* e = g_ET + (size_t)k * DDIM;
        float dot = 0.0f;
        for (int d = 0; d < DDIM; d++) dot = fmaf(zs[d], e[d], dot);
        float dv = fmaf(-2.0f, dot, g_e2[k]);
        if (dv < best) { best = dv; bi = k; }
    }
    __shared__ float sv[128];
    __shared__ int   si[128];
    sv[tid] = best; si[tid] = bi;
    __syncthreads();
    for (int s = 64; s > 0; s >>= 1) {
        if (tid < s) {
            float ov = sv[tid + s]; int oi = si[tid + s];
            if (ov < sv[tid] || (ov == sv[tid] && oi < si[tid])) { sv[tid] = ov; si[tid] = oi; }
        }
        __syncthreads();
    }
    if (tid == 0) g_idx[g_fixlist[i]] = si[0];
}

// counts + q gather + rowloss using FINAL indices
__global__ void vq_finish_kernel(float* __restrict__ qout) {
    const int row = blockIdx.x;
    const int tid = threadIdx.x;              // 128
    const int idx = g_idx[row];
    if (tid == 0) atomicAdd(&g_counts[idx], 1.0f);

    const float* e = g_ET + (size_t)idx * DDIM;
    const float* z = g_Z  + (size_t)row * DDIM;
    float ls = 0.0f;
    for (int d = tid; d < DDIM; d += 128) {
        float q = e[d], zz = z[d];
        qout[(size_t)row * DDIM + d] = q;
        float t = q - zz;
        ls = fmaf(t, t, ls);
    }
    __shared__ float sv[128];
    sv[tid] = ls;
    __syncthreads();
    for (int s = 64; s > 0; s >>= 1) { if (tid < s) sv[tid] += sv[tid + s]; __syncthreads(); }
    if (tid == 0) g_rowloss[row] = sv[0];
}

__global__ void vq_stats_kernel(const float* __restrict__ ema_cs, float* __restrict__ out) {
    const int k = threadIdx.x;
    __shared__ float red[512];
    __shared__ float shn, shent;
    float cnt = g_counts[k];
    float cs  = 0.99f * ema_cs[k] + 0.01f * cnt;
    red[k] = cs; __syncthreads();
    for (int s = 256; s > 0; s >>= 1) { if (k < s) red[k] += red[k + s]; __syncthreads(); }
    if (k == 0) shn = red[0];
    __syncthreads();
    float p = cnt * (1.0f / 16384.0f);
    red[k] = p * logf(p + 1e-10f);
    __syncthreads();
    for (int s = 256; s > 0; s >>= 1) { if (k < s) red[k] += red[k + s]; __syncthreads(); }
    if (k == 0) shent = red[0];
    __syncthreads();
    float ls = 0.0f;
    for (int r = k; r < BATCH; r += 512) ls += g_rowloss[r];
    red[k] = ls; __syncthreads();
    for (int s = 256; s > 0; s >>= 1) { if (k < s) red[k] += red[k + s]; __syncthreads(); }
    float n   = shn;
    float csn = (cs + 1e-5f) / (n + 512.0f * 1e-5f) * n;
    g_cs[k] = csn;
    out[OUT_CS + k] = csn;
    if (k == 0) {
        out[OUT_LOSS] = 0.25f * red[0] / 16777216.0f;
        out[OUT_PERP] = expf(-shent);
    }
}

__global__ void vq_dw_kernel() {
    const int k = blockIdx.x;
    const int tid = threadIdx.x;
    float a0 = 0.f, a1 = 0.f, a2 = 0.f, a3 = 0.f;
    __shared__ unsigned smask[8];
    for (int b0 = 0; b0 < BATCH; b0 += 256) {
        int mi = g_idx[b0 + tid];
        unsigned m = __ballot_sync(0xffffffffu, mi == k);
        if ((tid & 31) == 0) smask[tid >> 5] = m;
        __syncthreads();
#pragma unroll
        for (int w = 0; w < 8; w++) {
            unsigned mm = smask[w];
            while (mm) {
                int bit = __ffs(mm) - 1;
                mm &= mm - 1;
                const float* z = g_Z + (size_t)(b0 + w * 32 + bit) * DDIM;
                a0 += z[tid]; a1 += z[tid + 256]; a2 += z[tid + 512]; a3 += z[tid + 768];
            }
        }
        __syncthreads();
    }
    g_dwT[(size_t)k * DDIM + tid]       = a0;
    g_dwT[(size_t)k * DDIM + tid + 256] = a1;
    g_dwT[(size_t)k * DDIM + tid + 512] = a2;
    g_dwT[(size_t)k * DDIM + tid + 768] = a3;
}

__global__ void emb_out_kernel(const float* __restrict__ ema_dw, float* __restrict__ out) {
    __shared__ float t[32][33];
    int k0 = blockIdx.x * 32, d0 = blockIdx.y * 32;
    int tx = threadIdx.x, ty = threadIdx.y;
#pragma unroll
    for (int i = 0; i < 4; i++)
        t[ty + i * 8][tx] = g_dwT[(size_t)(k0 + ty + i * 8) * DDIM + d0 + tx];
    __syncthreads();
#pragma unroll
    for (int i = 0; i < 4; i++) {
        int d = d0 + ty + i * 8;
        int k = k0 + tx;
        float v = 0.99f * ema_dw[(size_t)d * KCB + k] + 0.01f * t[tx][ty + i * 8];
        out[OUT_EMB + (size_t)d * KCB + k] = v / g_cs[k];
    }
}

// ---------------- launcher ----------------
extern "C" void kernel_launch(void* const* d_in, const int* in_sizes, int n_in,
                              void* d_out, int out_size) {
    const float* obs    = (const float*)d_in[0];
    const float* action = (const float*)d_in[1];
    const float* nobs   = (const float*)d_in[2];
    const float* rew    = (const float*)d_in[3];
    const float* term   = (const float*)d_in[4];
    const float* w0 = (const float*)d_in[5];
    const float* b0 = (const float*)d_in[6];
    const float* w1 = (const float*)d_in[7];
    const float* b1 = (const float*)d_in[8];
    const float* w2 = (const float*)d_in[9];
    const float* b2 = (const float*)d_in[10];
    const float* w3 = (const float*)d_in[11];
    const float* b3 = (const float*)d_in[12];
    const float* wl = (const float*)d_in[13];
    const float* bl = (const float*)d_in[14];
    const float* emb    = (const float*)d_in[15];
    const float* ema_cs = (const float*)d_in[16];
    const float* ema_dw = (const float*)d_in[17];
    float* out = (float*)d_out;

    __half *pXh, *pW0h, *pW1h, *pW2h, *pW3h, *pWLh, *pA1h, *pA2h;
    float *pZ, *pS, *pW0f, *pXa, *pHa, *pHb, *pZa;
    int *pNfix;
    cudaGetSymbolAddress((void**)&pXh,  g_Xh);
    cudaGetSymbolAddress((void**)&pW0h, g_W0h);
    cudaGetSymbolAddress((void**)&pW1h, g_W1h);
    cudaGetSymbolAddress((void**)&pW2h, g_W2h);
    cudaGetSymbolAddress((void**)&pW3h, g_W3h);
    cudaGetSymbolAddress((void**)&pWLh, g_WLh);
    cudaGetSymbolAddress((void**)&pA1h, g_A1h);
    cudaGetSymbolAddress((void**)&pA2h, g_A2h);
    cudaGetSymbolAddress((void**)&pZ,   g_Z);
    cudaGetSymbolAddress((void**)&pS,   g_S);
    cudaGetSymbolAddress((void**)&pW0f, g_W0f);
    cudaGetSymbolAddress((void**)&pXa,  g_Xa);
    cudaGetSymbolAddress((void**)&pHa,  g_Ha);
    cudaGetSymbolAddress((void**)&pHb,  g_Hb);
    cudaGetSymbolAddress((void**)&pZa,  g_Za);
    cudaGetSymbolAddress((void**)&pNfix, g_nfix);

    cudaFuncSetAttribute(hmma_kernel<true,  true,  false>, cudaFuncAttributeMaxDynamicSharedMemorySize, SMEMSZ);
    cudaFuncSetAttribute(hmma_kernel<false, false, true >, cudaFuncAttributeMaxDynamicSharedMemorySize, SMEMSZ);

    const float is256 = 1.0f / 256.0f;

    // launches 1-5 (skipped by ncu -s 5): zero, pack_x0, tsplit_w0, tsplit_w1, pack_w0f
    zero_counts_kernel<<<2, 256>>>();
    pack_x0_kernel<<<dim3(9, BATCH), 128>>>(obs, action, nobs, rew, term);
    tsplit_kernel<<<dim3(DINP/32, HDIM/32), dim3(32, 8)>>>(w0, DIN,  HDIM, pW0h, DINP, 256.0f);
    tsplit_kernel<<<dim3(HDIM/32, HDIM/32), dim3(32, 8)>>>(w1, HDIM, HDIM, pW1h, HDIM, 256.0f);
    pack_w0f_kernel<<<dim3(32, DINP), 128>>>(w0);

    // launch 6 (ncu captures this): hmma L0
    hmma_kernel<true,  true,  false><<<dim3(HDIM/128, BATCH/128), 256, SMEMSZ>>>(pXh,  pW0h, b0, pA1h, nullptr, DINP, HDIM, is256);
    tsplit_kernel<<<dim3(HDIM/32, HDIM/32), dim3(32, 8)>>>(w2, HDIM, HDIM, pW2h, HDIM, 256.0f);
    hmma_kernel<true,  true,  false><<<dim3(HDIM/128, BATCH/128), 256, SMEMSZ>>>(pA1h, pW1h, b1, pA2h, nullptr, HDIM, HDIM, is256);
    tsplit_kernel<<<dim3(HDIM/32, HDIM/32), dim3(32, 8)>>>(w3, HDIM, HDIM, pW3h, HDIM, 256.0f);
    hmma_kernel<true,  true,  false><<<dim3(HDIM/128, BATCH/128), 256, SMEMSZ>>>(pA2h, pW2h, b2, pA1h, nullptr, HDIM, HDIM, is256);
    tsplit_kernel<<<dim3(HDIM/32, DDIM/32), dim3(32, 8)>>>(wl, HDIM, DDIM, pWLh, HDIM, 256.0f);
    hmma_kernel<true,  true,  false><<<dim3(HDIM/128, BATCH/128), 256, SMEMSZ>>>(pA1h, pW3h, b3, pA2h, nullptr, HDIM, HDIM, is256);
    prep_et_kernel<<<dim3(KCB/32, DDIM/32), dim3(32, 8)>>>(emb);
    hmma_kernel<false, false, true ><<<dim3(DDIM/128, BATCH/128), 256, SMEMSZ>>>(pA2h, pWLh, bl, nullptr, pZ, HDIM, DDIM, is256);
    prep_e2_kernel<<<2, 256>>>(emb);

    // S = z @ embeddings in fp32
    sgemm_kernel<false><<<dim3(KCB/128, BATCH/128), 256>>>(pZ, emb, nullptr, pS, KCB, DDIM, nullptr);

    // argmin + ambiguity flagging
    vq_row_kernel<<<BATCH, 128>>>();

    // exact fp32 repair for ambiguous rows (split-K8 for low latency; no-ops when none)
    gather_fix_kernel<<<dim3(9, RMAX), 128>>>(obs, action, nobs, rew, term);
    sgemm_splitk_kernel<<<dim3(HDIM/128, RMAX/128, NSLICE), 256>>>(pXa, pW0f, HDIM, DINP, pNfix);
    reduce_kernel<true ><<<dim3(HDIM/256, RMAX), 256>>>(b0, pHa, HDIM, pNfix);
    sgemm_splitk_kernel<<<dim3(HDIM/128, RMAX/128, NSLICE), 256>>>(pHa, w1, HDIM, HDIM, pNfix);
    reduce_kernel<true ><<<dim3(HDIM/256, RMAX), 256>>>(b1, pHb, HDIM, pNfix);
    sgemm_splitk_kernel<<<dim3(HDIM/128, RMAX/128, NSLICE), 256>>>(pHb, w2, HDIM, HDIM, pNfix);
    reduce_kernel<true ><<<dim3(HDIM/256, RMAX), 256>>>(b2, pHa, HDIM, pNfix);
    sgemm_splitk_kernel<<<dim3(HDIM/128, RMAX/128, NSLICE), 256>>>(pHa, w3, HDIM, HDIM, pNfix);
    reduce_kernel<true ><<<dim3(HDIM/256, RMAX), 256>>>(b3, pHb, HDIM, pNfix);
    sgemm_splitk_kernel<<<dim3(DDIM/128, RMAX/128, NSLICE), 256>>>(pHb, wl, DDIM, HDIM, pNfix);
    reduce_kernel<false><<<dim3(DDIM/256, RMAX), 256>>>(bl, pZa, DDIM, pNfix);
    repair_argmin_kernel<<<RMAX, 128>>>();

    // finish VQ with final indices
    vq_finish_kernel<<<BATCH, 128>>>(out);
    vq_stats_kernel<<<1, 512>>>(ema_cs, out);
    vq_dw_kernel<<<KCB, 256>>>();
    emb_out_kernel<<<dim3(KCB/32, DDIM/32), dim3(32, 8)>>>(ema_dw, out);
}

// round 17
// speedup vs baseline: 1.0887x; 1.0233x over previous
#include <cuda_runtime.h>
#include <cuda_fp16.h>
#include <math.h>
#include <stdint.h>

// ---------------- problem constants ----------------
#define BATCH 16384
#define HDIM  4096
#define DDIM  1024
#define KCB   512
#define DIN   1090
#define DINP  1152
#define RMAX  2048
#define ARG_TH 0.30f
#define NSLICE 8

#define OUT_Q    0
#define OUT_LOSS 16777216
#define OUT_PERP 16777217
#define OUT_EMB  16777218
#define OUT_CS   17301506

// ---------------- scratch (device globals; no allocation) ----------------
__device__ __half g_Xh [(size_t)BATCH * DINP];
__device__ __half g_W0h[(size_t)HDIM * DINP];
__device__ __half g_W1h[(size_t)HDIM * HDIM];
__device__ __half g_W2h[(size_t)HDIM * HDIM];
__device__ __half g_W3h[(size_t)HDIM * HDIM];
__device__ __half g_WLh[(size_t)DDIM * HDIM];
__device__ __half g_A1h[(size_t)BATCH * HDIM];
__device__ __half g_A2h[(size_t)BATCH * HDIM];
__device__ __half g_Zh [(size_t)BATCH * DDIM];
__device__ __half g_Eh [(size_t)KCB  * DDIM];
__device__ float  g_Z  [(size_t)BATCH * DDIM];
__device__ float  g_S  [(size_t)BATCH * KCB];
__device__ float  g_ET [(size_t)KCB * DDIM];
__device__ float  g_e2 [KCB];
__device__ int    g_idx[BATCH];
__device__ float  g_counts[KCB];
__device__ float  g_cs [KCB];
__device__ float  g_rowloss[BATCH];
__device__ float  g_dwT[(size_t)KCB * DDIM];
// repair path
__device__ int    g_nfix;
__device__ int    g_fixlist[RMAX];
__device__ float  g_W0f[(size_t)DINP * HDIM];
__device__ float  g_Xa [(size_t)RMAX * DINP];
__device__ float  g_Ha [(size_t)RMAX * HDIM];
__device__ float  g_Hb [(size_t)RMAX * HDIM];
__device__ float  g_Za [(size_t)RMAX * DDIM];
__device__ float  g_P  [(size_t)NSLICE * RMAX * HDIM];   // split-K partials

// ---------------- PTX helpers (all baseline sm_80-class) ----------------
__device__ __forceinline__ uint32_t smem_u32(const void* p) {
    uint32_t a;
    asm("{ .reg .u64 t; cvta.to.shared.u64 t, %1; cvt.u32.u64 %0, t; }" : "=r"(a) : "l"(p));
    return a;
}
__device__ __forceinline__ void cpa16(uint32_t s, const void* g) {
    asm volatile("cp.async.cg.shared.global [%0], [%1], 16;" :: "r"(s), "l"(g));
}
#define CP_COMMIT() asm volatile("cp.async.commit_group;" ::: "memory")

__device__ __forceinline__ void ldsm4(uint32_t* r, uint32_t a) {
    asm volatile("ldmatrix.sync.aligned.m8n8.x4.shared.b16 {%0,%1,%2,%3}, [%4];"
                 : "=r"(r[0]), "=r"(r[1]), "=r"(r[2]), "=r"(r[3]) : "r"(a));
}
__device__ __forceinline__ void mma16816(float* c, const uint32_t* a, uint32_t b0, uint32_t b1) {
    asm volatile("mma.sync.aligned.m16n8k16.row.col.f32.f16.f16.f32 "
                 "{%0,%1,%2,%3}, {%4,%5,%6,%7}, {%8,%9}, {%0,%1,%2,%3};"
                 : "+f"(c[0]), "+f"(c[1]), "+f"(c[2]), "+f"(c[3])
                 : "r"(a[0]), "r"(a[1]), "r"(a[2]), "r"(a[3]), "r"(b0), "r"(b1));
}

// ---------------- prep kernels ----------------
__global__ void zero_counts_kernel() {
    g_counts[blockIdx.x * 256 + threadIdx.x] = 0.0f;
    if (blockIdx.x == 0 && threadIdx.x == 0) g_nfix = 0;
}

__global__ void pack_x0_kernel(const float* __restrict__ obs, const float* __restrict__ act,
                               const float* __restrict__ nobs, const float* __restrict__ rew,
                               const float* __restrict__ term) {
    int k = blockIdx.x * 128 + threadIdx.x;   // 0..1151
    int r = blockIdx.y;
    float v;
    if (k < 512)        v = obs [r * 512 + k];
    else if (k < 576)   v = act [r * 64  + (k - 512)];
    else if (k < 1088)  v = nobs[r * 512 + (k - 576)];
    else if (k == 1088) v = rew [r];
    else if (k == 1089) v = term[r];
    else                v = 0.0f;
    g_Xh[(size_t)r * DINP + k] = __float2half_rn(v);
}

// pad w0 [1090,4096] -> fp32 [1152,4096] (repair path)
__global__ void pack_w0f_kernel(const float* __restrict__ w0) {
    int c = blockIdx.x * 128 + threadIdx.x;   // grid.x = 32
    int r = blockIdx.y;                        // 0..1151
    g_W0f[(size_t)r * HDIM + c] = (r < DIN) ? w0[(size_t)r * HDIM + c] : 0.0f;
}

// src [Rv valid rows (K-dim), N] row-major -> dh [N][Kd] transposed, quantized, scaled
__global__ void tsplit_kernel(const float* __restrict__ src, int Rv, int N,
                              __half* __restrict__ dh, int Kd, float scale) {
    __shared__ float t[32][33];
    int k0 = blockIdx.x * 32, n0 = blockIdx.y * 32;
    int tx = threadIdx.x, ty = threadIdx.y;   // (32,8)
#pragma unroll
    for (int i = 0; i < 4; i++) {
        int k = k0 + ty + i * 8;
        t[ty + i * 8][tx] = (k < Rv) ? src[(size_t)k * N + n0 + tx] * scale : 0.0f;
    }
    __syncthreads();
#pragma unroll
    for (int i = 0; i < 4; i++) {
        int n = n0 + ty + i * 8;
        int k = k0 + tx;
        dh[(size_t)n * Kd + k] = __float2half_rn(t[tx][ty + i * 8]);
    }
}

__global__ void prep_et_kernel(const float* __restrict__ E) {
    __shared__ float t[32][33];
    int k0 = blockIdx.x * 32, d0 = blockIdx.y * 32;
    int tx = threadIdx.x, ty = threadIdx.y;
#pragma unroll
    for (int i = 0; i < 4; i++)
        t[ty + i * 8][tx] = E[(size_t)(d0 + ty + i * 8) * KCB + k0 + tx];
    __syncthreads();
#pragma unroll
    for (int i = 0; i < 4; i++)
        g_ET[(size_t)(k0 + ty + i * 8) * DDIM + d0 + tx] = t[tx][ty + i * 8];
}

__global__ void prep_e2_kernel(const float* __restrict__ E) {
    int k = blockIdx.x * 256 + threadIdx.x;
    float s = 0.0f;
    for (int d = 0; d < DDIM; d++) { float v = E[(size_t)d * KCB + k]; s = fmaf(v, v, s); }
    g_e2[k] = s;
}

// ---------------- 1-term fp16 HMMA GEMM: Ah @ Bh^T, fp32 acc ----------------
// 3-stage cp.async pipeline, single barrier per K-step, warp grid 4m x 2n.
#define ST_H   5120                 // halves per matrix tile (128*40)
#define STAGE_H (2 * ST_H)          // Ah | Bh
#define SMEMSZ (3 * STAGE_H * 2)    // bytes (61440)

template<bool RELU, bool WPACK, bool WF32>
__global__ void __launch_bounds__(256, 2)
hmma_kernel(const __half* __restrict__ Ah, const __half* __restrict__ Bh,
            const float* __restrict__ bias,
            __half* __restrict__ Ch, float* __restrict__ Cf,
            int K, int Ntot, float invs) {
    extern __shared__ __align__(16) __half sm[];
    const uint32_t smb = smem_u32(sm);
    const int tid  = threadIdx.x;
    const int wid  = tid >> 5;
    const int lane = tid & 31;
    const int wm   = wid & 3;
    const int wn   = wid >> 2;
    const int m0 = blockIdx.y * 128;
    const int n0 = blockIdx.x * 128;
    const int nkt = K >> 5;

    float acc[2][8][4] = {};

    const int lrow = tid >> 2;
    const int lc   = tid & 3;

#define LOADST(kt, s) do {                                                        \
        const size_t gk = (size_t)(kt) * 32 + lc * 8;                             \
        const uint32_t sb = smb + (uint32_t)(s) * (STAGE_H * 2);                  \
        _Pragma("unroll")                                                         \
        for (int i_ = 0; i_ < 2; i_++) {                                          \
            const int r_ = lrow + 64 * i_;                                        \
            const uint32_t so = (uint32_t)(r_ * 40 + lc * 8) * 2;                 \
            cpa16(sb + so,               Ah + (size_t)(m0 + r_) * K + gk);        \
            cpa16(sb + so + ST_H * 2,    Bh + (size_t)(n0 + r_) * K + gk);        \
        }                                                                         \
        CP_COMMIT();                                                              \
    } while (0)

    LOADST(0, 0);
    LOADST(1, 1);

    const int ar  = wm * 32 + (lane & 15);
    const int acx = (lane >> 4) * 8;

    for (int kt = 0; kt < nkt; kt++) {
        const int s = kt % 3;
        if (kt + 1 < nkt) asm volatile("cp.async.wait_group 1;" ::: "memory");
        else              asm volatile("cp.async.wait_group 0;" ::: "memory");
        __syncthreads();
        if (kt + 2 < nkt) LOADST(kt + 2, (kt + 2) % 3);

        const uint32_t sb = smb + (uint32_t)s * (STAGE_H * 2);
#pragma unroll
        for (int kk = 0; kk < 32; kk += 16) {
            uint32_t ah[2][4];
#pragma unroll
            for (int mt = 0; mt < 2; mt++) {
                const uint32_t ao = (uint32_t)((ar + mt * 16) * 40 + kk + acx) * 2;
                ldsm4(ah[mt], sb + ao);
            }
#pragma unroll
            for (int nt = 0; nt < 4; nt++) {
                const int br = wn * 64 + nt * 16 + (lane & 15);
                const uint32_t bo = (uint32_t)(br * 40 + kk + acx) * 2;
                uint32_t bh[4];
                ldsm4(bh, sb + bo + ST_H * 2);
#pragma unroll
                for (int mt = 0; mt < 2; mt++) {
                    mma16816(acc[mt][2 * nt],     ah[mt], bh[0], bh[2]);
                    mma16816(acc[mt][2 * nt + 1], ah[mt], bh[1], bh[3]);
                }
            }
        }
    }

    const int erow = lane >> 2;
    const int ecol = 2 * (lane & 3);
#pragma unroll
    for (int mt = 0; mt < 2; mt++) {
#pragma unroll
        for (int j = 0; j < 8; j++) {
            const int n = n0 + wn * 64 + j * 8 + ecol;
            float bz0 = 0.f, bz1 = 0.f;
            if (bias) { bz0 = __ldg(&bias[n]); bz1 = __ldg(&bias[n + 1]); }
#pragma unroll
            for (int h = 0; h < 2; h++) {
                const int m = m0 + wm * 32 + mt * 16 + erow + h * 8;
                float v0 = acc[mt][j][2 * h]     * invs + bz0;
                float v1 = acc[mt][j][2 * h + 1] * invs + bz1;
                if (RELU) { v0 = fmaxf(v0, 0.f); v1 = fmaxf(v1, 0.f); }
                const size_t o = (size_t)m * Ntot + n;
                if (WPACK) {
                    *(__half2*)(Ch + o) = __halves2half2(__float2half_rn(v0), __float2half_rn(v1));
                }
                if (WF32) {
                    *(float2*)(Cf + o) = make_float2(v0, v1);
                }
            }
        }
    }
}

// ---------------- fp32 split-K SGEMM (repair; deterministic, NSLICE slices) ----------------
__global__ __launch_bounds__(256, 2)
void sgemm_splitk_kernel(const float* __restrict__ A, const float* __restrict__ B,
                         int N, int K, const int* limit) {
    if ((int)blockIdx.y * 128 >= min(*limit, RMAX)) return;
    const int Ks = K / NSLICE;
    const int sl = blockIdx.z;
    const int k0 = sl * Ks;
    __shared__ float As[8][128];
    __shared__ float Bs[8][128];
    const int tid = threadIdx.x;
    const int bx = blockIdx.x, by = blockIdx.y;
    const float* Ab = A + (size_t)by * 128 * K + k0;
    const float* Bb = B + (size_t)k0 * N + (size_t)bx * 128;
    const int aRow = tid >> 1, aCol = (tid & 1) * 4;
    const int bRow = tid >> 5, bCol = (tid & 31) * 4;
    const int tx = (tid & 15) * 8, ty = (tid >> 4) * 8;
    float acc[8][8] = {};

    for (int kt = 0; kt < Ks; kt += 8) {
        float4 av = *reinterpret_cast<const float4*>(Ab + (size_t)aRow * K + kt + aCol);
        float4 bv = *reinterpret_cast<const float4*>(Bb + (size_t)(kt + bRow) * N + bCol);
        As[aCol + 0][aRow] = av.x;
        As[aCol + 1][aRow] = av.y;
        As[aCol + 2][aRow] = av.z;
        As[aCol + 3][aRow] = av.w;
        *reinterpret_cast<float4*>(&Bs[bRow][bCol]) = bv;
        __syncthreads();
#pragma unroll
        for (int kk = 0; kk < 8; kk++) {
            float a[8], b[8];
            *reinterpret_cast<float4*>(&a[0]) = *reinterpret_cast<const float4*>(&As[kk][ty]);
            *reinterpret_cast<float4*>(&a[4]) = *reinterpret_cast<const float4*>(&As[kk][ty + 4]);
            *reinterpret_cast<float4*>(&b[0]) = *reinterpret_cast<const float4*>(&Bs[kk][tx]);
            *reinterpret_cast<float4*>(&b[4]) = *reinterpret_cast<const float4*>(&Bs[kk][tx + 4]);
#pragma unroll
            for (int i = 0; i < 8; i++)
#pragma unroll
                for (int j = 0; j < 8; j++)
                    acc[i][j] = fmaf(a[i], b[j], acc[i][j]);
        }
        __syncthreads();
    }
#pragma unroll
    for (int i = 0; i < 8; i++) {
        float* Cp = g_P + ((size_t)sl * RMAX + by * 128 + ty + i) * N + bx * 128 + tx;
        *reinterpret_cast<float4*>(Cp)     = *reinterpret_cast<float4*>(&acc[i][0]);
        *reinterpret_cast<float4*>(Cp + 4) = *reinterpret_cast<float4*>(&acc[i][4]);
    }
}

// deterministic fixed-order reduce of NSLICE partials (+bias)(+relu)
template<bool RELU>
__global__ void reduce_kernel(const float* __restrict__ bias, float* __restrict__ C,
                              int N, const int* limit) {
    const int r = blockIdx.y;
    if (r >= min(*limit, RMAX)) return;
    const int c = blockIdx.x * 256 + threadIdx.x;
    float v = bias ? bias[c] : 0.0f;
#pragma unroll
    for (int s = 0; s < NSLICE; s++)
        v += g_P[((size_t)s * RMAX + r) * N + c];
    if (RELU) v = fmaxf(v, 0.0f);
    C[(size_t)r * N + c] = v;
}

// ---------------- VQ: argmin + ambiguity detection ----------------
__global__ void vq_row_kernel() {
    const int row = blockIdx.x;
    const int tid = threadIdx.x;              // 128
    const float* Sr = g_S + (size_t)row * KCB;

    float best = 3.4e38f; int bi = 0;
    for (int k = tid; k < KCB; k += 128) {
        float dv = fmaf(-2.0f, Sr[k], g_e2[k]);
        if (dv < best) { best = dv; bi = k; }
    }
    __shared__ float sv[128];
    __shared__ int   si[128];
    sv[tid] = best; si[tid] = bi;
    __syncthreads();
    for (int s = 64; s > 0; s >>= 1) {
        if (tid < s) {
            float ov = sv[tid + s]; int oi = si[tid + s];
            if (ov < sv[tid] || (ov == sv[tid] && oi < si[tid])) { sv[tid] = ov; si[tid] = oi; }
        }
        __syncthreads();
    }
    const int idx = si[0];
    const float d1 = sv[0];
    __syncthreads();

    float b2 = 3.4e38f;
    for (int k = tid; k < KCB; k += 128) {
        if (k == idx) continue;
        float dv = fmaf(-2.0f, Sr[k], g_e2[k]);
        b2 = fminf(b2, dv);
    }
    sv[tid] = b2;
    __syncthreads();
    for (int s = 64; s > 0; s >>= 1) {
        if (tid < s) sv[tid] = fminf(sv[tid], sv[tid + s]);
        __syncthreads();
    }

    if (tid == 0) {
        g_idx[row] = idx;
        if (sv[0] - d1 < ARG_TH) {
            int slot = atomicAdd(&g_nfix, 1);
            if (slot < RMAX) g_fixlist[slot] = row;
        }
    }
}

// gather padded fp32 X rows for the repair batch
__global__ void gather_fix_kernel(const float* __restrict__ obs, const float* __restrict__ act,
                                  const float* __restrict__ nobs, const float* __restrict__ rew,
                                  const float* __restrict__ term) {
    const int i = blockIdx.y;
    if (i >= min(g_nfix, RMAX)) return;
    const int r = g_fixlist[i];
    const int k = blockIdx.x * 128 + threadIdx.x;
    float v;
    if (k < 512)        v = obs [r * 512 + k];
    else if (k < 576)   v = act [r * 64  + (k - 512)];
    else if (k < 1088)  v = nobs[r * 512 + (k - 576)];
    else if (k == 1088) v = rew [r];
    else if (k == 1089) v = term[r];
    else                v = 0.0f;
    g_Xa[(size_t)i * DINP + k] = v;
}

// exact fp32 argmin for repaired rows
__global__ void repair_argmin_kernel() {
    const int i = blockIdx.x;
    if (i >= min(g_nfix, RMAX)) return;
    const int tid = threadIdx.x;              // 128
    __shared__ float zs[DDIM];
    const float* za = g_Za + (size_t)i * DDIM;
    for (int d = tid; d < DDIM; d += 128) zs[d] = za[d];
    __syncthreads();

    float best = 3.4e38f; int bi = 0;
    for (int k = tid; k < KCB; k += 128) {
        const float* e = g_ET + (size_t)k * DDIM;
        float dot = 0.0f;
        for (int d = 0; d < DDIM; d++) dot = fmaf(zs[d], e[d], dot);
        float dv = fmaf(-2.0f, dot, g_e2[k]);
        if (dv < best) { best = dv; bi = k; }
    }
    __shared__ float sv[128];
    __shared__ int   si[128];
    sv[tid] = best; si[tid] = bi;
    __syncthreads();
    for (int s = 64; s > 0; s >>= 1) {
        if (tid < s) {
            float ov = sv[tid + s]; int oi = si[tid + s];
            if (ov < sv[tid] || (ov == sv[tid] && oi < si[tid])) { sv[tid] = ov; si[tid] = oi; }
        }
        __syncthreads();
    }
    if (tid == 0) g_idx[g_fixlist[i]] = si[0];
}

// counts + q gather + rowloss using FINAL indices
__global__ void vq_finish_kernel(float* __restrict__ qout) {
    const int row = blockIdx.x;
    const int tid = threadIdx.x;              // 128
    const int idx = g_idx[row];
    if (tid == 0) atomicAdd(&g_counts[idx], 1.0f);

    const float* e = g_ET + (size_t)idx * DDIM;
    const float* z = g_Z  + (size_t)row * DDIM;
    float ls = 0.0f;
    for (int d = tid; d < DDIM; d += 128) {
        float q = e[d], zz = z[d];
        qout[(size_t)row * DDIM + d] = q;
        float t = q - zz;
        ls = fmaf(t, t, ls);
    }
    __shared__ float sv[128];
    sv[tid] = ls;
    __syncthreads();
    for (int s = 64; s > 0; s >>= 1) { if (tid < s) sv[tid] += sv[tid + s]; __syncthreads(); }
    if (tid == 0) g_rowloss[row] = sv[0];
}

__global__ void vq_stats_kernel(const float* __restrict__ ema_cs, float* __restrict__ out) {
    const int k = threadIdx.x;
    __shared__ float red[512];
    __shared__ float shn, shent;
    float cnt = g_counts[k];
    float cs  = 0.99f * ema_cs[k] + 0.01f * cnt;
    red[k] = cs; __syncthreads();
    for (int s = 256; s > 0; s >>= 1) { if (k < s) red[k] += red[k + s]; __syncthreads(); }
    if (k == 0) shn = red[0];
    __syncthreads();
    float p = cnt * (1.0f / 16384.0f);
    red[k] = p * logf(p + 1e-10f);
    __syncthreads();
    for (int s = 256; s > 0; s >>= 1) { if (k < s) red[k] += red[k + s]; __syncthreads(); }
    if (k == 0) shent = red[0];
    __syncthreads();
    float ls = 0.0f;
    for (int r = k; r < BATCH; r += 512) ls += g_rowloss[r];
    red[k] = ls; __syncthreads();
    for (int s = 256; s > 0; s >>= 1) { if (k < s) red[k] += red[k + s]; __syncthreads(); }
    float n   = shn;
    float csn = (cs + 1e-5f) / (n + 512.0f * 1e-5f) * n;
    g_cs[k] = csn;
    out[OUT_CS + k] = csn;
    if (k == 0) {
        out[OUT_LOSS] = 0.25f * red[0] / 16777216.0f;
        out[OUT_PERP] = expf(-shent);
    }
}

__global__ void vq_dw_kernel() {
    const int k = blockIdx.x;
    const int tid = threadIdx.x;
    float a0 = 0.f, a1 = 0.f, a2 = 0.f, a3 = 0.f;
    __shared__ unsigned smask[8];
    for (int b0 = 0; b0 < BATCH; b0 += 256) {
        int mi = g_idx[b0 + tid];
        unsigned m = __ballot_sync(0xffffffffu, mi == k);
        if ((tid & 31) == 0) smask[tid >> 5] = m;
        __syncthreads();
#pragma unroll
        for (int w = 0; w < 8; w++) {
            unsigned mm = smask[w];
            while (mm) {
                int bit = __ffs(mm) - 1;
                mm &= mm - 1;
                const float* z = g_Z + (size_t)(b0 + w * 32 + bit) * DDIM;
                a0 += z[tid]; a1 += z[tid + 256]; a2 += z[tid + 512]; a3 += z[tid + 768];
            }
        }
        __syncthreads();
    }
    g_dwT[(size_t)k * DDIM + tid]       = a0;
    g_dwT[(size_t)k * DDIM + tid + 256] = a1;
    g_dwT[(size_t)k * DDIM + tid + 512] = a2;
    g_dwT[(size_t)k * DDIM + tid + 768] = a3;
}

__global__ void emb_out_kernel(const float* __restrict__ ema_dw, float* __restrict__ out) {
    __shared__ float t[32][33];
    int k0 = blockIdx.x * 32, d0 = blockIdx.y * 32;
    int tx = threadIdx.x, ty = threadIdx.y;
#pragma unroll
    for (int i = 0; i < 4; i++)
        t[ty + i * 8][tx] = g_dwT[(size_t)(k0 + ty + i * 8) * DDIM + d0 + tx];
    __syncthreads();
#pragma unroll
    for (int i = 0; i < 4; i++) {
        int d = d0 + ty + i * 8;
        int k = k0 + tx;
        float v = 0.99f * ema_dw[(size_t)d * KCB + k] + 0.01f * t[tx][ty + i * 8];
        out[OUT_EMB + (size_t)d * KCB + k] = v / g_cs[k];
    }
}

// ---------------- launcher ----------------
extern "C" void kernel_launch(void* const* d_in, const int* in_sizes, int n_in,
                              void* d_out, int out_size) {
    const float* obs    = (const float*)d_in[0];
    const float* action = (const float*)d_in[1];
    const float* nobs   = (const float*)d_in[2];
    const float* rew    = (const float*)d_in[3];
    const float* term   = (const float*)d_in[4];
    const float* w0 = (const float*)d_in[5];
    const float* b0 = (const float*)d_in[6];
    const float* w1 = (const float*)d_in[7];
    const float* b1 = (const float*)d_in[8];
    const float* w2 = (const float*)d_in[9];
    const float* b2 = (const float*)d_in[10];
    const float* w3 = (const float*)d_in[11];
    const float* b3 = (const float*)d_in[12];
    const float* wl = (const float*)d_in[13];
    const float* bl = (const float*)d_in[14];
    const float* emb    = (const float*)d_in[15];
    const float* ema_cs = (const float*)d_in[16];
    const float* ema_dw = (const float*)d_in[17];
    float* out = (float*)d_out;

    __half *pXh, *pW0h, *pW1h, *pW2h, *pW3h, *pWLh, *pA1h, *pA2h, *pZh, *pEh;
    float *pZ, *pS, *pW0f, *pXa, *pHa, *pHb, *pZa;
    int *pNfix;
    cudaGetSymbolAddress((void**)&pXh,  g_Xh);
    cudaGetSymbolAddress((void**)&pW0h, g_W0h);
    cudaGetSymbolAddress((void**)&pW1h, g_W1h);
    cudaGetSymbolAddress((void**)&pW2h, g_W2h);
    cudaGetSymbolAddress((void**)&pW3h, g_W3h);
    cudaGetSymbolAddress((void**)&pWLh, g_WLh);
    cudaGetSymbolAddress((void**)&pA1h, g_A1h);
    cudaGetSymbolAddress((void**)&pA2h, g_A2h);
    cudaGetSymbolAddress((void**)&pZh,  g_Zh);
    cudaGetSymbolAddress((void**)&pEh,  g_Eh);
    cudaGetSymbolAddress((void**)&pZ,   g_Z);
    cudaGetSymbolAddress((void**)&pS,   g_S);
    cudaGetSymbolAddress((void**)&pW0f, g_W0f);
    cudaGetSymbolAddress((void**)&pXa,  g_Xa);
    cudaGetSymbolAddress((void**)&pHa,  g_Ha);
    cudaGetSymbolAddress((void**)&pHb,  g_Hb);
    cudaGetSymbolAddress((void**)&pZa,  g_Za);
    cudaGetSymbolAddress((void**)&pNfix, g_nfix);

    cudaFuncSetAttribute(hmma_kernel<true,  true,  false>, cudaFuncAttributeMaxDynamicSharedMemorySize, SMEMSZ);
    cudaFuncSetAttribute(hmma_kernel<false, true,  true >, cudaFuncAttributeMaxDynamicSharedMemorySize, SMEMSZ);
    cudaFuncSetAttribute(hmma_kernel<false, false, true >, cudaFuncAttributeMaxDynamicSharedMemorySize, SMEMSZ);

    const float is256 = 1.0f / 256.0f;

    // launches 1-5 (skipped by ncu -s 5)
    zero_counts_kernel<<<2, 256>>>();
    pack_x0_kernel<<<dim3(9, BATCH), 128>>>(obs, action, nobs, rew, term);
    tsplit_kernel<<<dim3(DINP/32, HDIM/32), dim3(32, 8)>>>(w0, DIN,  HDIM, pW0h, DINP, 256.0f);
    tsplit_kernel<<<dim3(HDIM/32, HDIM/32), dim3(32, 8)>>>(w1, HDIM, HDIM, pW1h, HDIM, 256.0f);
    pack_w0f_kernel<<<dim3(32, DINP), 128>>>(w0);

    // launch 6 (ncu captures this): hmma L0
    hmma_kernel<true,  true,  false><<<dim3(HDIM/128, BATCH/128), 256, SMEMSZ>>>(pXh,  pW0h, b0, pA1h, nullptr, DINP, HDIM, is256);
    tsplit_kernel<<<dim3(HDIM/32, HDIM/32), dim3(32, 8)>>>(w2, HDIM, HDIM, pW2h, HDIM, 256.0f);
    hmma_kernel<true,  true,  false><<<dim3(HDIM/128, BATCH/128), 256, SMEMSZ>>>(pA1h, pW1h, b1, pA2h, nullptr, HDIM, HDIM, is256);
    tsplit_kernel<<<dim3(HDIM/32, HDIM/32), dim3(32, 8)>>>(w3, HDIM, HDIM, pW3h, HDIM, 256.0f);
    hmma_kernel<true,  true,  false><<<dim3(HDIM/128, BATCH/128), 256, SMEMSZ>>>(pA2h, pW2h, b2, pA1h, nullptr, HDIM, HDIM, is256);
    tsplit_kernel<<<dim3(HDIM/32, DDIM/32), dim3(32, 8)>>>(wl, HDIM, DDIM, pWLh, HDIM, 256.0f);
    hmma_kernel<true,  true,  false><<<dim3(HDIM/128, BATCH/128), 256, SMEMSZ>>>(pA1h, pW3h, b3, pA2h, nullptr, HDIM, HDIM, is256);
    prep_et_kernel<<<dim3(KCB/32, DDIM/32), dim3(32, 8)>>>(emb);
    tsplit_kernel<<<dim3(DDIM/32, KCB/32), dim3(32, 8)>>>(emb, DDIM, KCB, pEh, DDIM, 1.0f);
    // WL layer: emits fp32 z AND packed fp16 zh
    hmma_kernel<false, true,  true ><<<dim3(DDIM/128, BATCH/128), 256, SMEMSZ>>>(pA2h, pWLh, bl, pZh, pZ, HDIM, DDIM, is256);
    prep_e2_kernel<<<2, 256>>>(emb);

    // S = z @ embeddings via 1-term HMMA (noise gated by ARG_TH repair net)
    hmma_kernel<false, false, true ><<<dim3(KCB/128, BATCH/128), 256, SMEMSZ>>>(pZh, pEh, nullptr, nullptr, pS, DDIM, KCB, 1.0f);

    // argmin + ambiguity flagging
    vq_row_kernel<<<BATCH, 128>>>();

    // exact fp32 repair for ambiguous rows (split-K8; no-ops when none)
    gather_fix_kernel<<<dim3(9, RMAX), 128>>>(obs, action, nobs, rew, term);
    sgemm_splitk_kernel<<<dim3(HDIM/128, RMAX/128, NSLICE), 256>>>(pXa, pW0f, HDIM, DINP, pNfix);
    reduce_kernel<true ><<<dim3(HDIM/256, RMAX), 256>>>(b0, pHa, HDIM, pNfix);
    sgemm_splitk_kernel<<<dim3(HDIM/128, RMAX/128, NSLICE), 256>>>(pHa, w1, HDIM, HDIM, pNfix);
    reduce_kernel<true ><<<dim3(HDIM/256, RMAX), 256>>>(b1, pHb, HDIM, pNfix);
    sgemm_splitk_kernel<<<dim3(HDIM/128, RMAX/128, NSLICE), 256>>>(pHb, w2, HDIM, HDIM, pNfix);
    reduce_kernel<true ><<<dim3(HDIM/256, RMAX), 256>>>(b2, pHa, HDIM, pNfix);
    sgemm_splitk_kernel<<<dim3(HDIM/128, RMAX/128, NSLICE), 256>>>(pHa, w3, HDIM, HDIM, pNfix);
    reduce_kernel<true ><<<dim3(HDIM/256, RMAX), 256>>>(b3, pHb, HDIM, pNfix);
    sgemm_splitk_kernel<<<dim3(DDIM/128, RMAX/128, NSLICE), 256>>>(pHb, wl, DDIM, HDIM, pNfix);
    reduce_kernel<false><<<dim3(DDIM/256, RMAX), 256>>>(bl, pZa, DDIM, pNfix);
    repair_argmin_kernel<<<RMAX, 128>>>();

    // finish VQ with final indices
    vq_finish_kernel<<<BATCH, 128>>>(out);
    vq_stats_kernel<<<1, 512>>>(ema_cs, out);
    vq_dw_kernel<<<KCB, 256>>>();
    emb_out_kernel<<<dim3(KCB/32, DDIM/32), dim3(32, 8)>>>(ema_dw, out);
}